// round 15
// baseline (speedup 1.0000x reference)
#include <cuda_runtime.h>
#include <cuda_fp16.h>
#include <cstdint>

#define D_DIM   512
#define K_DIM   112
#define BM      128
#define NTHR    256
#define NIT     16               // k-chunks of 32
#define LAMBDA_ 5.0f

// SMEM layout (bytes)
#define A_STRIDE   80
#define A_HALF     (BM * A_STRIDE)           // 10240
#define A_STAGE    (2 * A_HALF)              // 20480
#define B_OFF      (2 * A_STAGE)             // 40960
#define B_STAGE    14336
#define NBSTG      3
#define SMEM_BYTES (B_OFF + NBSTG * B_STAGE) // 83968
#define SIMSP      114
#define W5_OFF     (BM * SIMSP * 4)          // 58368
#define I5_OFF     (W5_OFF + BM * 5 * 4)     // 60928 (ends 63488 < 83968)

// B fragments in mma order: [kh(32)][hl(2)][tile(14)][lane(32)] x uint2{b0,b1}
__device__ __align__(16) uint2 g_bfrag[32 * 2 * 14 * 32];

__device__ __forceinline__ uint32_t smem_u32(const void* p) {
    uint32_t a;
    asm("{ .reg .u64 t; cvta.to.shared.u64 t, %1; cvt.u32.u64 %0, t; }" : "=r"(a) : "l"(p));
    return a;
}
__device__ __forceinline__ void splith(float a, float b, uint32_t& hi, uint32_t& lo) {
    __half2 h = __floats2half2_rn(a, b);
    float2  f = __half22float2(h);
    __half2 l = __floats2half2_rn(a - f.x, b - f.y);
    hi = *(uint32_t*)&h;
    lo = *(uint32_t*)&l;
}

#define LDSM4(r, addr) \
    asm volatile("ldmatrix.sync.aligned.m8n8.x4.shared.b16 {%0,%1,%2,%3}, [%4];" \
                 : "=r"((r)[0]), "=r"((r)[1]), "=r"((r)[2]), "=r"((r)[3]) : "r"(addr))

#define MMA(d, a, b0, b1) \
    asm volatile("mma.sync.aligned.m16n8k16.row.col.f32.f16.f16.f32 " \
                 "{%0,%1,%2,%3}, {%4,%5,%6,%7}, {%8,%9}, {%0,%1,%2,%3};" \
                 : "+f"((d)[0]), "+f"((d)[1]), "+f"((d)[2]), "+f"((d)[3]) \
                 : "r"((a)[0]), "r"((a)[1]), "r"((a)[2]), "r"((a)[3]), "r"(b0), "r"(b1))

#define CPASYNC16(dst, src) \
    asm volatile("cp.async.cg.shared.global [%0], [%1], 16;" :: "r"(dst), "l"(src) : "memory")
#define CP_COMMIT()  asm volatile("cp.async.commit_group;" ::: "memory")
#define CP_WAIT1()   asm volatile("cp.async.wait_group 1;" ::: "memory")

// ---- pre-kernel: bake C into mma B-fragment order (hi/lo fp16 split) ----
__global__ void cc_frag_kernel(const float* __restrict__ cc) {
    int kh = blockIdx.x / 14, n8 = blockIdx.x % 14;
    int l = threadIdx.x;
    int n  = n8 * 8 + (l >> 2);
    int k0 = kh * 16 + (l & 3) * 2;
    uint32_t b0h, b0l, b1h, b1l;
    splith(cc[n * D_DIM + k0],     cc[n * D_DIM + k0 + 1], b0h, b0l);
    splith(cc[n * D_DIM + k0 + 8], cc[n * D_DIM + k0 + 9], b1h, b1l);
    g_bfrag[((kh * 2 + 0) * 14 + n8) * 32 + l] = make_uint2(b0h, b1h);
    g_bfrag[((kh * 2 + 1) * 14 + n8) * 32 + l] = make_uint2(b0l, b1l);
}

__global__ __launch_bounds__(NTHR, 2)
void tse_hmma9_kernel(const float* __restrict__ x,
                      const float* __restrict__ cc,
                      float* __restrict__ out)
{
    extern __shared__ unsigned char smem[];
    const uint32_t sb = smem_u32(smem);
    const int tid = threadIdx.x;
    const int w   = tid >> 5;
    const int l   = tid & 31;
    const int mg  = w & 3;          // rows mg*32 .. mg*32+31
    const int nh  = w >> 2;         // cols nh*56 .. nh*56+55
    const int nb7 = nh * 7;
    const int row0 = blockIdx.x * BM;

    float d[2][7][4];
    #pragma unroll
    for (int m = 0; m < 2; m++)
        #pragma unroll
        for (int p = 0; p < 7; p++)
            #pragma unroll
            for (int j = 0; j < 4; j++) d[m][p][j] = 0.0f;

    const uint32_t aOff = (uint32_t)(mg * 32 + (l & 15)) * A_STRIDE + ((l >> 4) << 4);

    const int srow0 = tid >> 3;
    const int sseg  = tid & 7;
    float4 px[4];

    auto FETCH = [&](int it) {
        #pragma unroll
        for (int i = 0; i < 4; i++)
            px[i] = *(const float4*)&x[(size_t)(row0 + srow0 + 32 * i) * D_DIM + it * 32 + sseg * 4];
    };
    auto STOREA = [&](int s) {
        unsigned char* st = smem + s * A_STAGE;
        #pragma unroll
        for (int i = 0; i < 4; i++) {
            uint32_t h0, l0, h1, l1;
            splith(px[i].x, px[i].y, h0, l0);
            splith(px[i].z, px[i].w, h1, l1);
            uint32_t off = (uint32_t)(srow0 + 32 * i) * A_STRIDE + sseg * 8;
            *(uint2*)(st + off)          = make_uint2(h0, h1);
            *(uint2*)(st + A_HALF + off) = make_uint2(l0, l1);
        }
    };
    auto CPB = [&](int it) {
        const char* src = (const char*)g_bfrag + (size_t)it * B_STAGE;
        uint32_t dst = sb + B_OFF + (it % NBSTG) * B_STAGE;
        #pragma unroll
        for (int i = 0; i < 4; i++) {
            int idx = tid + 256 * i;                 // 896 x 16B total
            if (i < 3 || idx < 896)
                CPASYNC16(dst + idx * 16, src + idx * 16);
        }
        CP_COMMIT();
    };

    // prologue: two B stages in flight
    CPB(0);
    CPB(1);
    FETCH(0);
    STOREA(0);

    for (int it = 0; it < NIT; it++) {
        CP_WAIT1();                         // B(it) resident (B(it+1) may be in flight)
        __syncthreads();
        if (it + 2 < NIT) CPB(it + 2);
        if (it + 1 < NIT) FETCH(it + 1);

        const uint32_t aBase = sb + (it & 1) * A_STAGE + aOff;
        const uint2* Bst = (const uint2*)(smem + B_OFF + (it % NBSTG) * B_STAGE);

        #pragma unroll
        for (int h = 0; h < 2; h++) {
            uint32_t ah[2][4], al[2][4];
            LDSM4(ah[0], aBase + h * 32);
            LDSM4(ah[1], aBase + 16 * A_STRIDE + h * 32);
            LDSM4(al[0], aBase + A_HALF + h * 32);
            LDSM4(al[1], aBase + A_HALF + 16 * A_STRIDE + h * 32);

            uint2 b[7];
            #pragma unroll
            for (int p = 0; p < 7; p++)
                b[p] = Bst[((h * 2 + 0) * 14 + nb7 + p) * 32 + l];   // hi frags
            // accumulator reuse distance = 14 (was 2)
            #pragma unroll
            for (int p = 0; p < 7; p++) {
                MMA(d[0][p], ah[0], b[p].x, b[p].y);
                MMA(d[1][p], ah[1], b[p].x, b[p].y);
            }
            #pragma unroll
            for (int p = 0; p < 7; p++) {
                MMA(d[0][p], al[0], b[p].x, b[p].y);
                MMA(d[1][p], al[1], b[p].x, b[p].y);
            }
            #pragma unroll
            for (int p = 0; p < 7; p++)
                b[p] = Bst[((h * 2 + 1) * 14 + nb7 + p) * 32 + l];   // lo frags
            #pragma unroll
            for (int p = 0; p < 7; p++) {
                MMA(d[0][p], ah[0], b[p].x, b[p].y);
                MMA(d[1][p], ah[1], b[p].x, b[p].y);
            }
        }

        if (it + 1 < NIT) STOREA((it + 1) & 1);
    }
    __syncthreads();

    // ---- dump sims to smem (overlays GEMM buffers) ----
    float* sims = (float*)smem;
    {
        int c0 = nh * 56 + (l & 3) * 2;
        #pragma unroll
        for (int m = 0; m < 2; m++) {
            int r1 = mg * 32 + m * 16 + (l >> 2);
            int r2 = r1 + 8;
            #pragma unroll
            for (int p = 0; p < 7; p++) {
                *(float2*)&sims[r1 * SIMSP + c0 + p * 8] = make_float2(d[m][p][0], d[m][p][1]);
                *(float2*)&sims[r2 * SIMSP + c0 + p * 8] = make_float2(d[m][p][2], d[m][p][3]);
            }
        }
    }
    __syncthreads();

    // ---- per-row top-5 + softmax ----
    float* w5 = (float*)(smem + W5_OFF);
    int*   i5 = (int*)(smem + I5_OFF);
    if (tid < BM) {
        const float* sr = &sims[tid * SIMSP];
        float v0 = -1e30f, v1 = -1e30f, v2 = -1e30f, v3 = -1e30f, v4 = -1e30f;
        int   i0 = 0, i1 = 0, i2 = 0, i3 = 0, i4 = 0;
        for (int c = 0; c < K_DIM; c++) {
            float s = sr[c];
            if (s > v4) {                       // strict >: earliest index wins ties
                v4 = s; i4 = c;
                if (v4 > v3) { float t=v3; v3=v4; v4=t; int q=i3; i3=i4; i4=q; }
                if (v3 > v2) { float t=v2; v2=v3; v3=t; int q=i2; i2=i3; i3=q; }
                if (v2 > v1) { float t=v1; v1=v2; v2=t; int q=i1; i1=i2; i2=q; }
                if (v1 > v0) { float t=v0; v0=v1; v1=t; int q=i0; i0=i1; i1=q; }
            }
        }
        float e1 = __expf(v1 - v0);
        float e2 = __expf(v2 - v0);
        float e3 = __expf(v3 - v0);
        float e4 = __expf(v4 - v0);
        float inv = LAMBDA_ / (1.0f + e1 + e2 + e3 + e4);
        w5[tid*5+0] = inv;      i5[tid*5+0] = i0;
        w5[tid*5+1] = e1 * inv; i5[tid*5+1] = i1;
        w5[tid*5+2] = e2 * inv; i5[tid*5+2] = i2;
        w5[tid*5+3] = e3 * inv; i5[tid*5+3] = i3;
        w5[tid*5+4] = e4 * inv; i5[tid*5+4] = i4;
    }
    __syncthreads();

    // ---- epilogue: warp-per-row, fully coalesced fp32 gather ----
    #pragma unroll 1
    for (int rr = 0; rr < 16; rr++) {
        int r = w * 16 + rr;
        float w0 = w5[r*5+0], w1 = w5[r*5+1], w2 = w5[r*5+2], w3 = w5[r*5+3], w4 = w5[r*5+4];
        int   j0 = i5[r*5+0], j1 = i5[r*5+1], j2 = i5[r*5+2], j3 = i5[r*5+3], j4 = i5[r*5+4];

        const float4* xp = (const float4*)&x[(size_t)(row0 + r) * D_DIM];
        float4*       op = (float4*)&out[(size_t)(row0 + r) * D_DIM];
        const float4* c0 = (const float4*)&cc[(size_t)j0 * D_DIM];
        const float4* c1 = (const float4*)&cc[(size_t)j1 * D_DIM];
        const float4* c2 = (const float4*)&cc[(size_t)j2 * D_DIM];
        const float4* c3 = (const float4*)&cc[(size_t)j3 * D_DIM];
        const float4* c4 = (const float4*)&cc[(size_t)j4 * D_DIM];

        #pragma unroll
        for (int i = 0; i < 4; i++) {
            int q = l + 32 * i;
            float4 xv = xp[q];
            float4 a0 = c0[q], a1 = c1[q], a2 = c2[q], a3 = c3[q], a4 = c4[q];
            float4 o;
            o.x = xv.x + w0*a0.x + w1*a1.x + w2*a2.x + w3*a3.x + w4*a4.x;
            o.y = xv.y + w0*a0.y + w1*a1.y + w2*a2.y + w3*a3.y + w4*a4.y;
            o.z = xv.z + w0*a0.z + w1*a1.z + w2*a2.z + w3*a3.z + w4*a4.z;
            o.w = xv.w + w0*a0.w + w1*a1.w + w2*a2.w + w3*a3.w + w4*a4.w;
            op[q] = o;
        }
    }
}

extern "C" void kernel_launch(void* const* d_in, const int* in_sizes, int n_in,
                              void* d_out, int out_size)
{
    const float* x  = (const float*)d_in[0];
    const float* cc = (const float*)d_in[1];
    int B = in_sizes[0] / D_DIM;

    cc_frag_kernel<<<32 * 14, 32>>>(cc);

    cudaFuncSetAttribute(tse_hmma9_kernel, cudaFuncAttributeMaxDynamicSharedMemorySize, SMEM_BYTES);
    tse_hmma9_kernel<<<B / BM, NTHR, SMEM_BYTES>>>(x, cc, (float*)d_out);
}

// round 16
// speedup vs baseline: 1.0224x; 1.0224x over previous
#include <cuda_runtime.h>
#include <cuda_fp16.h>
#include <cstdint>

#define D_DIM   512
#define K_DIM   112
#define BM      128
#define NTHR    256
#define NIT     16               // k-chunks of 32
#define LAMBDA_ 5.0f

// SMEM layout (bytes)
// A: per-mg pair regions, double buffered: [mg][stage][hi 32x80 | lo 32x80]
#define A_PAIR     10240                     // 2 stages x 5120
#define B_OFF      40960                     // 4 * A_PAIR
#define B_NH       21504                     // 3 stages x 7168 per nh group
#define GEMM_END   (B_OFF + 2 * B_NH)        // 83968
#define SIMSP      114
#define W5_OFF     GEMM_END                  // 83968
#define I5_OFF     (W5_OFF + BM * 5 * 4)     // 86528
#define SMEM_BYTES (I5_OFF + BM * 5 * 4)     // 89088

// B fragments pre-baked per (it,nh) slice, contiguous 7168B:
// [it(16)][nh(2)] x [h(2)][hl(2)][p(7)][lane(32)] uint2
__device__ __align__(16) uint2 g_bfrag[16 * 2 * 2 * 2 * 7 * 32];

__device__ __forceinline__ uint32_t smem_u32(const void* p) {
    uint32_t a;
    asm("{ .reg .u64 t; cvta.to.shared.u64 t, %1; cvt.u32.u64 %0, t; }" : "=r"(a) : "l"(p));
    return a;
}
__device__ __forceinline__ void splith(float a, float b, uint32_t& hi, uint32_t& lo) {
    __half2 h = __floats2half2_rn(a, b);
    float2  f = __half22float2(h);
    __half2 l = __floats2half2_rn(a - f.x, b - f.y);
    hi = *(uint32_t*)&h;
    lo = *(uint32_t*)&l;
}

#define BARN(id, cnt) asm volatile("bar.sync %0, %1;" :: "r"(id), "r"(cnt) : "memory")

#define LDSM4(r, addr) \
    asm volatile("ldmatrix.sync.aligned.m8n8.x4.shared.b16 {%0,%1,%2,%3}, [%4];" \
                 : "=r"((r)[0]), "=r"((r)[1]), "=r"((r)[2]), "=r"((r)[3]) : "r"(addr))

#define MMA(d, a, b0, b1) \
    asm volatile("mma.sync.aligned.m16n8k16.row.col.f32.f16.f16.f32 " \
                 "{%0,%1,%2,%3}, {%4,%5,%6,%7}, {%8,%9}, {%0,%1,%2,%3};" \
                 : "+f"((d)[0]), "+f"((d)[1]), "+f"((d)[2]), "+f"((d)[3]) \
                 : "r"((a)[0]), "r"((a)[1]), "r"((a)[2]), "r"((a)[3]), "r"(b0), "r"(b1))

#define CPASYNC16(dst, src) \
    asm volatile("cp.async.cg.shared.global [%0], [%1], 16;" :: "r"(dst), "l"(src) : "memory")
#define CP_COMMIT()  asm volatile("cp.async.commit_group;" ::: "memory")
#define CP_WAIT1()   asm volatile("cp.async.wait_group 1;" ::: "memory")
#define CP_WAIT0()   asm volatile("cp.async.wait_group 0;" ::: "memory")

// ---- pre-kernel: bake C into per-(it,nh) contiguous B fragment slices ----
__global__ void cc_frag_kernel(const float* __restrict__ cc) {
    int kh = blockIdx.x / 14, n8 = blockIdx.x % 14;
    int l = threadIdx.x;
    int n  = n8 * 8 + (l >> 2);
    int k0 = kh * 16 + (l & 3) * 2;
    uint32_t b0h, b0l, b1h, b1l;
    splith(cc[n * D_DIM + k0],     cc[n * D_DIM + k0 + 1], b0h, b0l);
    splith(cc[n * D_DIM + k0 + 8], cc[n * D_DIM + k0 + 9], b1h, b1l);
    int it = kh >> 1, h = kh & 1, nh = n8 / 7, p = n8 % 7;
    int base = (it * 2 + nh) * 28 + h * 14;            // tile index within global array
    g_bfrag[(base + 0 + p) * 32 + l] = make_uint2(b0h, b1h);   // hl = 0 (hi)
    g_bfrag[(base + 7 + p) * 32 + l] = make_uint2(b0l, b1l);   // hl = 1 (lo)
}

__global__ __launch_bounds__(NTHR, 2)
void tse_hmma10_kernel(const float* __restrict__ x,
                       const float* __restrict__ cc,
                       float* __restrict__ out)
{
    extern __shared__ unsigned char smem[];
    const uint32_t sb = smem_u32(smem);
    const int tid = threadIdx.x;
    const int w   = tid >> 5;
    const int l   = tid & 31;
    const int mg  = w & 3;           // rows mg*32 .. mg*32+31
    const int nh  = w >> 2;          // cols nh*56 .. nh*56+55
    const int g   = tid & 127;       // index within nh group (4 warps)
    const int pt  = nh * 32 + l;     // index within mg pair (2 warps)
    const int row0 = blockIdx.x * BM;

    float d[2][7][4];
    #pragma unroll
    for (int m = 0; m < 2; m++)
        #pragma unroll
        for (int p = 0; p < 7; p++)
            #pragma unroll
            for (int j = 0; j < 4; j++) d[m][p][j] = 0.0f;

    const uint32_t pairBase = sb + mg * A_PAIR;
    const uint32_t aOff = (uint32_t)(l & 15) * 80 + ((l >> 4) << 4);

    // x fetch: pair loads its 32 rows x 128B, perfectly coalesced per LDG.128
    const int frow = (pt >> 3);          // + 8*i
    const int fseg = pt & 7;
    float4 px[4];

    auto FETCH = [&](int it) {
        #pragma unroll
        for (int i = 0; i < 4; i++)
            px[i] = *(const float4*)&x[(size_t)(row0 + mg * 32 + i * 8 + frow) * D_DIM
                                        + it * 32 + fseg * 4];
    };
    auto STOREA = [&](int s) {
        uint32_t st = pairBase + s * 5120;
        #pragma unroll
        for (int i = 0; i < 4; i++) {
            uint32_t h0, l0, h1, l1;
            splith(px[i].x, px[i].y, h0, l0);
            splith(px[i].z, px[i].w, h1, l1);
            uint32_t off = (uint32_t)(i * 8 + frow) * 80 + fseg * 8;
            *(uint2*)(smem + (st - sb) + off)        = make_uint2(h0, h1);
            *(uint2*)(smem + (st - sb) + 2560 + off) = make_uint2(l0, l1);
        }
    };
    auto CPB = [&](int it) {
        const char* src = (const char*)g_bfrag + (size_t)(it * 2 + nh) * 7168;
        uint32_t dst = sb + B_OFF + nh * B_NH + (it % 3) * 7168;
        #pragma unroll
        for (int i = 0; i < 4; i++) {
            int idx = g + 128 * i;                   // 448 x 16B per slice
            if (i < 3 || idx < 448)
                CPASYNC16(dst + idx * 16, src + idx * 16);
        }
        CP_COMMIT();
    };

    // prologue: two B slices in flight, A(0) staged
    CPB(0);
    CPB(1);
    FETCH(0);
    STOREA(0);
    BARN(1 + mg, 64);

    for (int it = 0; it < NIT; it++) {
        if (it == NIT - 1) CP_WAIT0(); else CP_WAIT1();
        BARN(5 + nh, 128);                      // B(it) visible to the 4-warp group
        if (it + 2 < NIT) CPB(it + 2);
        if (it + 1 < NIT) FETCH(it + 1);

        const uint32_t aBase = pairBase + (it & 1) * 5120 + aOff;
        const uint2* Bst = (const uint2*)(smem + B_OFF + nh * B_NH + (it % 3) * 7168);

        #pragma unroll
        for (int h = 0; h < 2; h++) {
            uint32_t ah[2][4], al[2][4];
            LDSM4(ah[0], aBase + h * 32);
            LDSM4(ah[1], aBase + 1280 + h * 32);          // +16 rows * 80B
            LDSM4(al[0], aBase + 2560 + h * 32);
            LDSM4(al[1], aBase + 2560 + 1280 + h * 32);

            uint2 b[7];
            #pragma unroll
            for (int p = 0; p < 7; p++)
                b[p] = Bst[((h * 2 + 0) * 7 + p) * 32 + l];      // hi frags
            #pragma unroll
            for (int p = 0; p < 7; p++) {
                MMA(d[0][p], ah[0], b[p].x, b[p].y);
                MMA(d[1][p], ah[1], b[p].x, b[p].y);
                MMA(d[0][p], al[0], b[p].x, b[p].y);
                MMA(d[1][p], al[1], b[p].x, b[p].y);
            }
            #pragma unroll
            for (int p = 0; p < 7; p++)
                b[p] = Bst[((h * 2 + 1) * 7 + p) * 32 + l];      // lo frags
            #pragma unroll
            for (int p = 0; p < 7; p++) {
                MMA(d[0][p], ah[0], b[p].x, b[p].y);
                MMA(d[1][p], ah[1], b[p].x, b[p].y);
            }
        }

        if (it + 1 < NIT) {
            STOREA((it + 1) & 1);
            BARN(1 + mg, 64);                   // A(it+1) staged for the pair
        }
    }
    __syncthreads();

    // ---- dump sims to smem (overlays GEMM buffers) ----
    float* sims = (float*)smem;
    {
        int c0 = nh * 56 + (l & 3) * 2;
        #pragma unroll
        for (int m = 0; m < 2; m++) {
            int r1 = mg * 32 + m * 16 + (l >> 2);
            int r2 = r1 + 8;
            #pragma unroll
            for (int p = 0; p < 7; p++) {
                *(float2*)&sims[r1 * SIMSP + c0 + p * 8] = make_float2(d[m][p][0], d[m][p][1]);
                *(float2*)&sims[r2 * SIMSP + c0 + p * 8] = make_float2(d[m][p][2], d[m][p][3]);
            }
        }
    }
    __syncthreads();

    // ---- per-row top-5 + softmax ----
    float* w5 = (float*)(smem + W5_OFF);
    int*   i5 = (int*)(smem + I5_OFF);
    if (tid < BM) {
        const float* sr = &sims[tid * SIMSP];
        float v0 = -1e30f, v1 = -1e30f, v2 = -1e30f, v3 = -1e30f, v4 = -1e30f;
        int   i0 = 0, i1 = 0, i2 = 0, i3 = 0, i4 = 0;
        for (int c = 0; c < K_DIM; c++) {
            float s = sr[c];
            if (s > v4) {                       // strict >: earliest index wins ties
                v4 = s; i4 = c;
                if (v4 > v3) { float t=v3; v3=v4; v4=t; int q=i3; i3=i4; i4=q; }
                if (v3 > v2) { float t=v2; v2=v3; v3=t; int q=i2; i2=i3; i3=q; }
                if (v2 > v1) { float t=v1; v1=v2; v2=t; int q=i1; i1=i2; i2=q; }
                if (v1 > v0) { float t=v0; v0=v1; v1=t; int q=i0; i0=i1; i1=q; }
            }
        }
        float e1 = __expf(v1 - v0);
        float e2 = __expf(v2 - v0);
        float e3 = __expf(v3 - v0);
        float e4 = __expf(v4 - v0);
        float inv = LAMBDA_ / (1.0f + e1 + e2 + e3 + e4);
        w5[tid*5+0] = inv;      i5[tid*5+0] = i0;
        w5[tid*5+1] = e1 * inv; i5[tid*5+1] = i1;
        w5[tid*5+2] = e2 * inv; i5[tid*5+2] = i2;
        w5[tid*5+3] = e3 * inv; i5[tid*5+3] = i3;
        w5[tid*5+4] = e4 * inv; i5[tid*5+4] = i4;
    }
    __syncthreads();

    // ---- epilogue: warp-per-row, fully coalesced fp32 gather ----
    #pragma unroll 1
    for (int rr = 0; rr < 16; rr++) {
        int r = w * 16 + rr;
        float w0 = w5[r*5+0], w1 = w5[r*5+1], w2 = w5[r*5+2], w3 = w5[r*5+3], w4 = w5[r*5+4];
        int   j0 = i5[r*5+0], j1 = i5[r*5+1], j2 = i5[r*5+2], j3 = i5[r*5+3], j4 = i5[r*5+4];

        const float4* xp = (const float4*)&x[(size_t)(row0 + r) * D_DIM];
        float4*       op = (float4*)&out[(size_t)(row0 + r) * D_DIM];
        const float4* c0 = (const float4*)&cc[(size_t)j0 * D_DIM];
        const float4* c1 = (const float4*)&cc[(size_t)j1 * D_DIM];
        const float4* c2 = (const float4*)&cc[(size_t)j2 * D_DIM];
        const float4* c3 = (const float4*)&cc[(size_t)j3 * D_DIM];
        const float4* c4 = (const float4*)&cc[(size_t)j4 * D_DIM];

        #pragma unroll
        for (int i = 0; i < 4; i++) {
            int q = l + 32 * i;
            float4 xv = xp[q];
            float4 a0 = c0[q], a1 = c1[q], a2 = c2[q], a3 = c3[q], a4 = c4[q];
            float4 o;
            o.x = xv.x + w0*a0.x + w1*a1.x + w2*a2.x + w3*a3.x + w4*a4.x;
            o.y = xv.y + w0*a0.y + w1*a1.y + w2*a2.y + w3*a3.y + w4*a4.y;
            o.z = xv.z + w0*a0.z + w1*a1.z + w2*a2.z + w3*a3.z + w4*a4.z;
            o.w = xv.w + w0*a0.w + w1*a1.w + w2*a2.w + w3*a3.w + w4*a4.w;
            op[q] = o;
        }
    }
}

extern "C" void kernel_launch(void* const* d_in, const int* in_sizes, int n_in,
                              void* d_out, int out_size)
{
    const float* x  = (const float*)d_in[0];
    const float* cc = (const float*)d_in[1];
    int B = in_sizes[0] / D_DIM;

    cc_frag_kernel<<<32 * 14, 32>>>(cc);

    cudaFuncSetAttribute(tse_hmma10_kernel, cudaFuncAttributeMaxDynamicSharedMemorySize, SMEM_BYTES);
    tse_hmma10_kernel<<<B / BM, NTHR, SMEM_BYTES>>>(x, cc, (float*)d_out);
}

// round 17
// speedup vs baseline: 1.1474x; 1.1222x over previous
#include <cuda_runtime.h>
#include <cuda_fp16.h>
#include <cstdint>

#define D_DIM   512
#define K_DIM   112
#define BM      128
#define NTHR    256
#define NIT     16               // k-chunks of 32
#define LAMBDA_ 5.0f

// SMEM layout (bytes)
#define A_STRIDE   80
#define A_HALF     (BM * A_STRIDE)           // 10240
#define A_STAGE    (2 * A_HALF)              // 20480
#define B_OFF      (2 * A_STAGE)             // 40960
#define B_STAGE    14336
#define SIMSP      114
#define SIMS_B     (BM * SIMSP * 4)          // 58368
#define CANDV_OFF  SIMS_B                    // 58368  (256 x 5 floats)
#define CANDI_OFF  (CANDV_OFF + NTHR * 5 * 4)   // 63488
#define W5_OFF     (CANDI_OFF + NTHR * 5 * 4)   // 68608
#define I5_OFF     (W5_OFF + BM * 5 * 4)        // 71168
#define SMEM_BYTES 73728

// B fragments in mma order: [kh(32)][hl(2)][tile(14)][lane(32)] x uint2{b0,b1}
__device__ __align__(16) uint2 g_bfrag[32 * 2 * 14 * 32];

__device__ __forceinline__ uint32_t smem_u32(const void* p) {
    uint32_t a;
    asm("{ .reg .u64 t; cvta.to.shared.u64 t, %1; cvt.u32.u64 %0, t; }" : "=r"(a) : "l"(p));
    return a;
}
__device__ __forceinline__ void splith(float a, float b, uint32_t& hi, uint32_t& lo) {
    __half2 h = __floats2half2_rn(a, b);
    float2  f = __half22float2(h);
    __half2 l = __floats2half2_rn(a - f.x, b - f.y);
    hi = *(uint32_t*)&h;
    lo = *(uint32_t*)&l;
}

#define LDSM4(r, addr) \
    asm volatile("ldmatrix.sync.aligned.m8n8.x4.shared.b16 {%0,%1,%2,%3}, [%4];" \
                 : "=r"((r)[0]), "=r"((r)[1]), "=r"((r)[2]), "=r"((r)[3]) : "r"(addr))

#define MMA(d, a, b0, b1) \
    asm volatile("mma.sync.aligned.m16n8k16.row.col.f32.f16.f16.f32 " \
                 "{%0,%1,%2,%3}, {%4,%5,%6,%7}, {%8,%9}, {%0,%1,%2,%3};" \
                 : "+f"((d)[0]), "+f"((d)[1]), "+f"((d)[2]), "+f"((d)[3]) \
                 : "r"((a)[0]), "r"((a)[1]), "r"((a)[2]), "r"((a)[3]), "r"(b0), "r"(b1))

#define CPASYNC16(dst, src) \
    asm volatile("cp.async.cg.shared.global [%0], [%1], 16;" :: "r"(dst), "l"(src) : "memory")
#define CP_COMMIT()  asm volatile("cp.async.commit_group;" ::: "memory")
#define CP_WAIT0()   asm volatile("cp.async.wait_group 0;" ::: "memory")

// ---- pre-kernel: bake C into mma B-fragment order (hi/lo fp16 split) ----
__global__ void cc_frag_kernel(const float* __restrict__ cc) {
    int kh = blockIdx.x / 14, n8 = blockIdx.x % 14;
    int l = threadIdx.x;
    int n  = n8 * 8 + (l >> 2);
    int k0 = kh * 16 + (l & 3) * 2;
    uint32_t b0h, b0l, b1h, b1l;
    splith(cc[n * D_DIM + k0],     cc[n * D_DIM + k0 + 1], b0h, b0l);
    splith(cc[n * D_DIM + k0 + 8], cc[n * D_DIM + k0 + 9], b1h, b1l);
    g_bfrag[((kh * 2 + 0) * 14 + n8) * 32 + l] = make_uint2(b0h, b1h);
    g_bfrag[((kh * 2 + 1) * 14 + n8) * 32 + l] = make_uint2(b0l, b1l);
}

__global__ __launch_bounds__(NTHR, 2)
void tse_hmma11_kernel(const float* __restrict__ x,
                       const float* __restrict__ cc,
                       float* __restrict__ out)
{
    extern __shared__ unsigned char smem[];
    const uint32_t sb = smem_u32(smem);
    const int tid = threadIdx.x;
    const int w   = tid >> 5;
    const int l   = tid & 31;
    const int mg  = w & 3;          // rows mg*32 .. mg*32+31
    const int nh  = w >> 2;         // cols nh*56 .. nh*56+55
    const int nb7 = nh * 7;
    const int row0 = blockIdx.x * BM;

    float d[2][7][4];
    #pragma unroll
    for (int m = 0; m < 2; m++)
        #pragma unroll
        for (int p = 0; p < 7; p++)
            #pragma unroll
            for (int j = 0; j < 4; j++) d[m][p][j] = 0.0f;

    const uint32_t aOff = (uint32_t)(mg * 32 + (l & 15)) * A_STRIDE + ((l >> 4) << 4);

    const int srow0 = tid >> 3;
    const int sseg  = tid & 7;
    float4 px[4];

    auto FETCH = [&](int it) {
        #pragma unroll
        for (int i = 0; i < 4; i++)
            px[i] = *(const float4*)&x[(size_t)(row0 + srow0 + 32 * i) * D_DIM + it * 32 + sseg * 4];
    };
    auto STOREA = [&](int s) {
        unsigned char* st = smem + s * A_STAGE;
        #pragma unroll
        for (int i = 0; i < 4; i++) {
            uint32_t h0, l0, h1, l1;
            splith(px[i].x, px[i].y, h0, l0);
            splith(px[i].z, px[i].w, h1, l1);
            uint32_t off = (uint32_t)(srow0 + 32 * i) * A_STRIDE + sseg * 8;
            *(uint2*)(st + off)          = make_uint2(h0, h1);
            *(uint2*)(st + A_HALF + off) = make_uint2(l0, l1);
        }
    };
    auto CPB = [&](int it) {
        const char* src = (const char*)g_bfrag + (size_t)it * B_STAGE;
        uint32_t dst = sb + B_OFF + (it & 1) * B_STAGE;
        #pragma unroll
        for (int i = 0; i < 4; i++) {
            int idx = tid + 256 * i;                 // 896 x 16B total
            if (i < 3 || idx < 896)
                CPASYNC16(dst + idx * 16, src + idx * 16);
        }
        CP_COMMIT();
    };

    // prologue
    CPB(0);
    FETCH(0);
    STOREA(0);

    for (int it = 0; it < NIT; it++) {
        CP_WAIT0();
        __syncthreads();
        if (it + 1 < NIT) CPB(it + 1);
        if (it + 1 < NIT) FETCH(it + 1);

        const uint32_t aBase = sb + (it & 1) * A_STAGE + aOff;
        const uint2* Bst = (const uint2*)(smem + B_OFF + (it & 1) * B_STAGE);

        #pragma unroll
        for (int h = 0; h < 2; h++) {
            uint32_t ah[2][4], al[2][4];
            LDSM4(ah[0], aBase + h * 32);
            LDSM4(ah[1], aBase + 16 * A_STRIDE + h * 32);
            LDSM4(al[0], aBase + A_HALF + h * 32);
            LDSM4(al[1], aBase + A_HALF + 16 * A_STRIDE + h * 32);

            uint2 b[7];
            #pragma unroll
            for (int p = 0; p < 7; p++)
                b[p] = Bst[((h * 2 + 0) * 14 + nb7 + p) * 32 + l];   // hi frags
            #pragma unroll
            for (int p = 0; p < 7; p++) {
                MMA(d[0][p], ah[0], b[p].x, b[p].y);
                MMA(d[1][p], ah[1], b[p].x, b[p].y);
                MMA(d[0][p], al[0], b[p].x, b[p].y);
                MMA(d[1][p], al[1], b[p].x, b[p].y);
            }
            #pragma unroll
            for (int p = 0; p < 7; p++)
                b[p] = Bst[((h * 2 + 1) * 14 + nb7 + p) * 32 + l];   // lo frags
            #pragma unroll
            for (int p = 0; p < 7; p++) {
                MMA(d[0][p], ah[0], b[p].x, b[p].y);
                MMA(d[1][p], ah[1], b[p].x, b[p].y);
            }
        }

        if (it + 1 < NIT) STOREA((it + 1) & 1);
    }
    __syncthreads();

    // ---- dump sims to smem (overlays GEMM buffers) ----
    float* sims = (float*)smem;
    {
        int c0 = nh * 56 + (l & 3) * 2;
        #pragma unroll
        for (int m = 0; m < 2; m++) {
            int r1 = mg * 32 + m * 16 + (l >> 2);
            int r2 = r1 + 8;
            #pragma unroll
            for (int p = 0; p < 7; p++) {
                *(float2*)&sims[r1 * SIMSP + c0 + p * 8] = make_float2(d[m][p][0], d[m][p][1]);
                *(float2*)&sims[r2 * SIMSP + c0 + p * 8] = make_float2(d[m][p][2], d[m][p][3]);
            }
        }
    }
    __syncthreads();

    // ---- parallel top-5: 2 threads per row scan 56 cols each ----
    float* candv = (float*)(smem + CANDV_OFF);
    int*   candi = (int*)(smem + CANDI_OFF);
    {
        int row  = tid & 127;
        int half = tid >> 7;
        const float* sr = &sims[row * SIMSP + half * 56];
        int base = half * 56;
        float v0 = -1e30f, v1 = -1e30f, v2 = -1e30f, v3 = -1e30f, v4 = -1e30f;
        int   i0 = 0, i1 = 0, i2 = 0, i3 = 0, i4 = 0;
        for (int c = 0; c < 56; c++) {
            float s = sr[c];
            if (s > v4) {                       // strict >: earliest index wins ties
                v4 = s; i4 = base + c;
                if (v4 > v3) { float t=v3; v3=v4; v4=t; int q=i3; i3=i4; i4=q; }
                if (v3 > v2) { float t=v2; v2=v3; v3=t; int q=i2; i2=i3; i3=q; }
                if (v2 > v1) { float t=v1; v1=v2; v2=t; int q=i1; i1=i2; i2=q; }
                if (v1 > v0) { float t=v0; v0=v1; v1=t; int q=i0; i0=i1; i1=q; }
            }
        }
        candv[tid*5+0] = v0; candi[tid*5+0] = i0;
        candv[tid*5+1] = v1; candi[tid*5+1] = i1;
        candv[tid*5+2] = v2; candi[tid*5+2] = i2;
        candv[tid*5+3] = v3; candi[tid*5+3] = i3;
        candv[tid*5+4] = v4; candi[tid*5+4] = i4;
    }
    __syncthreads();

    // ---- merge two descending 5-lists per row + softmax ----
    float* w5 = (float*)(smem + W5_OFF);
    int*   i5 = (int*)(smem + I5_OFF);
    if (tid < BM) {
        int p0 = 0, p1 = 0;
        float mv[5]; int mi[5];
        #pragma unroll
        for (int k = 0; k < 5; k++) {
            float a = (p0 < 5) ? candv[tid*5+p0]       : -1e30f;
            float b = (p1 < 5) ? candv[(tid+128)*5+p1] : -1e30f;
            if (a >= b) {       // ties -> half 0 (smaller index), matches jax
                mv[k] = a; mi[k] = candi[tid*5+p0]; p0++;
            } else {
                mv[k] = b; mi[k] = candi[(tid+128)*5+p1]; p1++;
            }
        }
        float e1 = __expf(mv[1] - mv[0]);
        float e2 = __expf(mv[2] - mv[0]);
        float e3 = __expf(mv[3] - mv[0]);
        float e4 = __expf(mv[4] - mv[0]);
        float inv = LAMBDA_ / (1.0f + e1 + e2 + e3 + e4);
        w5[tid*5+0] = inv;      i5[tid*5+0] = mi[0];
        w5[tid*5+1] = e1 * inv; i5[tid*5+1] = mi[1];
        w5[tid*5+2] = e2 * inv; i5[tid*5+2] = mi[2];
        w5[tid*5+3] = e3 * inv; i5[tid*5+3] = mi[3];
        w5[tid*5+4] = e4 * inv; i5[tid*5+4] = mi[4];
    }
    __syncthreads();

    // ---- epilogue: warp-per-row-pair (2 rows in flight -> 2x MLP) ----
    #pragma unroll 1
    for (int rr = 0; rr < 16; rr += 2) {
        int ra = w * 16 + rr;
        int rb = ra + 1;
        float wa0 = w5[ra*5+0], wa1 = w5[ra*5+1], wa2 = w5[ra*5+2], wa3 = w5[ra*5+3], wa4 = w5[ra*5+4];
        float wb0 = w5[rb*5+0], wb1 = w5[rb*5+1], wb2 = w5[rb*5+2], wb3 = w5[rb*5+3], wb4 = w5[rb*5+4];
        int ja0 = i5[ra*5+0], ja1 = i5[ra*5+1], ja2 = i5[ra*5+2], ja3 = i5[ra*5+3], ja4 = i5[ra*5+4];
        int jb0 = i5[rb*5+0], jb1 = i5[rb*5+1], jb2 = i5[rb*5+2], jb3 = i5[rb*5+3], jb4 = i5[rb*5+4];

        const float4* xpa = (const float4*)&x[(size_t)(row0 + ra) * D_DIM];
        const float4* xpb = (const float4*)&x[(size_t)(row0 + rb) * D_DIM];
        float4* opa = (float4*)&out[(size_t)(row0 + ra) * D_DIM];
        float4* opb = (float4*)&out[(size_t)(row0 + rb) * D_DIM];
        const float4* ca0 = (const float4*)&cc[(size_t)ja0 * D_DIM];
        const float4* ca1 = (const float4*)&cc[(size_t)ja1 * D_DIM];
        const float4* ca2 = (const float4*)&cc[(size_t)ja2 * D_DIM];
        const float4* ca3 = (const float4*)&cc[(size_t)ja3 * D_DIM];
        const float4* ca4 = (const float4*)&cc[(size_t)ja4 * D_DIM];
        const float4* cb0 = (const float4*)&cc[(size_t)jb0 * D_DIM];
        const float4* cb1 = (const float4*)&cc[(size_t)jb1 * D_DIM];
        const float4* cb2 = (const float4*)&cc[(size_t)jb2 * D_DIM];
        const float4* cb3 = (const float4*)&cc[(size_t)jb3 * D_DIM];
        const float4* cb4 = (const float4*)&cc[(size_t)jb4 * D_DIM];

        #pragma unroll
        for (int i = 0; i < 4; i++) {
            int q = l + 32 * i;
            // 12 independent LDG.128 in flight
            float4 xva = xpa[q];
            float4 a0 = ca0[q], a1 = ca1[q], a2 = ca2[q], a3 = ca3[q], a4 = ca4[q];
            float4 xvb = xpb[q];
            float4 b0 = cb0[q], b1 = cb1[q], b2 = cb2[q], b3 = cb3[q], b4 = cb4[q];
            float4 oa, ob;
            oa.x = xva.x + wa0*a0.x + wa1*a1.x + wa2*a2.x + wa3*a3.x + wa4*a4.x;
            oa.y = xva.y + wa0*a0.y + wa1*a1.y + wa2*a2.y + wa3*a3.y + wa4*a4.y;
            oa.z = xva.z + wa0*a0.z + wa1*a1.z + wa2*a2.z + wa3*a3.z + wa4*a4.z;
            oa.w = xva.w + wa0*a0.w + wa1*a1.w + wa2*a2.w + wa3*a3.w + wa4*a4.w;
            ob.x = xvb.x + wb0*b0.x + wb1*b1.x + wb2*b2.x + wb3*b3.x + wb4*b4.x;
            ob.y = xvb.y + wb0*b0.y + wb1*b1.y + wb2*b2.y + wb3*b3.y + wb4*b4.y;
            ob.z = xvb.z + wb0*b0.z + wb1*b1.z + wb2*b2.z + wb3*b3.z + wb4*b4.z;
            ob.w = xvb.w + wb0*b0.w + wb1*b1.w + wb2*b2.w + wb3*b3.w + wb4*b4.w;
            opa[q] = oa;
            opb[q] = ob;
        }
    }
}

extern "C" void kernel_launch(void* const* d_in, const int* in_sizes, int n_in,
                              void* d_out, int out_size)
{
    const float* x  = (const float*)d_in[0];
    const float* cc = (const float*)d_in[1];
    int B = in_sizes[0] / D_DIM;

    cc_frag_kernel<<<32 * 14, 32>>>(cc);

    cudaFuncSetAttribute(tse_hmma11_kernel, cudaFuncAttributeMaxDynamicSharedMemorySize, SMEM_BYTES);
    tse_hmma11_kernel<<<B / BM, NTHR, SMEM_BYTES>>>(x, cc, (float*)d_out);
}